// round 13
// baseline (speedup 1.0000x reference)
#include <cuda_runtime.h>
#include <math.h>

// LSTM: T=1024, B=64, E=512, H=512, fp32.
//   1) pack_kernel : pack gate weights -> g_wx[512][2048], g_wh[512][2048], bias.
//   2) gemm_xproj  : x_proj[65536,2048] = embeds @ g_wx + bias  (SGEMM 128x128x16).
//   3) lstm_scan   : ONE persistent kernel, 128 co-resident blocks, software grid
//                    barrier per timestep. Wh slice resident in smem for all 1024 steps.
//
// Graph = 3 kernel nodes (fixes the 2MB graph-upload-pool teardown violation
// caused by the previous 1026-node graph).

#define T_LEN 1024
#define B_SZ  64
#define E_DIM 512
#define H_DIM 512
#define G4    2048
#define NBLK  128   // scan grid; must be <= 148 so all blocks are co-resident

// -------- device-global scratch (allocation-free rule) --------
__device__ __align__(16) float g_xp[(size_t)T_LEN * B_SZ * G4];  // 512 MB
__device__ __align__(16) float g_wx[E_DIM * G4];
__device__ __align__(16) float g_wh[H_DIM * G4];
__device__ __align__(16) float g_bias[G4];
__device__ unsigned g_arrive = 0;
__device__ unsigned g_epoch  = 0;

// ---------------- pack ----------------
__global__ void pack_kernel(const float* __restrict__ wgx, const float* __restrict__ wix,
                            const float* __restrict__ wfx, const float* __restrict__ wox,
                            const float* __restrict__ wgh, const float* __restrict__ wih,
                            const float* __restrict__ wfh, const float* __restrict__ woh,
                            const float* __restrict__ bg,  const float* __restrict__ bi,
                            const float* __restrict__ bf,  const float* __restrict__ bo)
{
    int idx = blockIdx.x * blockDim.x + threadIdx.x;
    const int total = E_DIM * G4;
    if (idx < total) {
        int k = idx >> 11;
        int c = idx & 2047;
        int g = c >> 9;
        int j = c & 511;
        const float* sx = (g == 0) ? wgx : (g == 1) ? wix : (g == 2) ? wfx : wox;
        const float* sh = (g == 0) ? wgh : (g == 1) ? wih : (g == 2) ? wfh : woh;
        g_wx[idx] = sx[k * H_DIM + j];
        g_wh[idx] = sh[k * H_DIM + j];
    }
    if (idx < G4) {
        int g = idx >> 9, j = idx & 511;
        const float* sb = (g == 0) ? bg : (g == 1) ? bi : (g == 2) ? bf : bo;
        g_bias[idx] = sb[j];
    }
}

// ---------------- x_proj SGEMM ----------------
__global__ void __launch_bounds__(256, 2) gemm_xproj(const float* __restrict__ A)
{
    __shared__ __align__(16) float As[16][128];
    __shared__ __align__(16) float Bs[16][128];

    const int tid = threadIdx.x;
    const int tx = tid & 15;
    const int ty = tid >> 4;
    const int n0 = blockIdx.x * 128;
    const int m0 = blockIdx.y * 128;

    float acc[8][8];
#pragma unroll
    for (int i = 0; i < 8; i++)
#pragma unroll
        for (int j = 0; j < 8; j++) acc[i][j] = 0.0f;

    for (int k0 = 0; k0 < E_DIM; k0 += 16) {
#pragma unroll
        for (int i = 0; i < 2; i++) {
            int id  = tid + i * 256;
            int row = id >> 2;
            int kq  = id & 3;
            float4 v = *(const float4*)(A + (size_t)(m0 + row) * E_DIM + k0 + kq * 4);
            As[kq * 4 + 0][row] = v.x;
            As[kq * 4 + 1][row] = v.y;
            As[kq * 4 + 2][row] = v.z;
            As[kq * 4 + 3][row] = v.w;
        }
#pragma unroll
        for (int i = 0; i < 2; i++) {
            int id = tid + i * 256;
            int kr = id >> 5;
            int nq = id & 31;
            float4 v = *(const float4*)(g_wx + (size_t)(k0 + kr) * G4 + n0 + nq * 4);
            *(float4*)(&Bs[kr][nq * 4]) = v;
        }
        __syncthreads();

#pragma unroll
        for (int kk = 0; kk < 16; kk++) {
            float a[8], b[8];
            *(float4*)&a[0] = *(float4*)&As[kk][ty * 8];
            *(float4*)&a[4] = *(float4*)&As[kk][ty * 8 + 4];
            *(float4*)&b[0] = *(float4*)&Bs[kk][tx * 8];
            *(float4*)&b[4] = *(float4*)&Bs[kk][tx * 8 + 4];
#pragma unroll
            for (int i = 0; i < 8; i++)
#pragma unroll
                for (int j = 0; j < 8; j++)
                    acc[i][j] = fmaf(a[i], b[j], acc[i][j]);
        }
        __syncthreads();
    }

    float bb[8];
#pragma unroll
    for (int j = 0; j < 8; j++) bb[j] = g_bias[n0 + tx * 8 + j];
#pragma unroll
    for (int i = 0; i < 8; i++) {
        int m = m0 + ty * 8 + i;
        float* crow = g_xp + (size_t)m * G4 + n0 + tx * 8;
        float4 v0, v1;
        v0.x = acc[i][0] + bb[0]; v0.y = acc[i][1] + bb[1];
        v0.z = acc[i][2] + bb[2]; v0.w = acc[i][3] + bb[3];
        v1.x = acc[i][4] + bb[4]; v1.y = acc[i][5] + bb[5];
        v1.z = acc[i][6] + bb[6]; v1.w = acc[i][7] + bb[7];
        *(float4*)(crow)     = v0;
        *(float4*)(crow + 4) = v1;
    }
}

// ---------------- persistent LSTM scan ----------------
// block = bt*32 + jt : bt in 0..3 (16-batch tile), jt in 0..31 (16-j tile, x4 gates).
// Shared memory (dynamic, 180224 B):
//   wt  [512][64]   : wt[k*64 + jl*4 + g]  (gate-interleaved weight slice, loaded ONCE)
//   h_sh[16][512]   : h_{t-1} batch tile
//   red [16][16][4][4] : k-split partial sums  [b_l][jl][g][ks]
// Threads = 256: compute role (ks,bq,jl) = (tid>>6, (tid>>4)&3, tid&15)
//               final  role (b_l,jl)    = (tid>>4, tid&15); c state in a register.
__global__ void __launch_bounds__(256, 1) lstm_scan(float* __restrict__ hs)
{
    extern __shared__ __align__(16) float smem[];
    float* wt   = smem;                    // 32768 floats
    float* h_sh = wt + 512 * 64;           // 8192 floats
    float* red  = h_sh + 16 * 512;         // 4096 floats

    const int tid = threadIdx.x;
    const int bt  = blockIdx.x >> 5;
    const int jt  = blockIdx.x & 31;
    const int b0  = bt * 16;
    const int j0  = jt * 16;

    // compute-role coords
    const int ks = tid >> 6;          // 0..3 (k chunk of 128)
    const int bq = (tid >> 4) & 3;    // 0..3 (4 batch rows)
    const int jl = tid & 15;          // 0..15

    // final-role coords
    const int fb = tid >> 4;          // 0..15 local batch row
    const int fj = tid & 15;          // 0..15 local j

    // ---- stage Wh slice once: wt[k*64 + jl2*4 + g] = Wh[k][g*512 + j0 + jl2] ----
    for (int i = tid; i < 512 * 16; i += 256) {
        int k = i >> 4;
        int s = i & 15;
        int g = s >> 2;
        int q = s & 3;               // float4 group of 4 local j
        float4 v = *(const float4*)(g_wh + (size_t)k * G4 + g * H_DIM + j0 + q * 4);
        float* d = wt + k * 64 + q * 16 + g;   // (q*4 + r)*4 + g
        d[0]  = v.x;
        d[4]  = v.y;
        d[8]  = v.z;
        d[12] = v.w;
    }

    unsigned epoch_base = 0;
    if (tid == 0) epoch_base = *(volatile unsigned*)&g_epoch;

    float c_reg = 0.0f;   // cell state for (b0+fb, j0+fj)

    for (int t = 0; t < T_LEN; t++) {
        // ---- stage h_{t-1} tile ----
        if (t == 0) {
            float4 z4 = make_float4(0.f, 0.f, 0.f, 0.f);
            for (int i = tid; i < 2048; i += 256)
                ((float4*)h_sh)[i] = z4;
        } else {
            const float* hp = hs + ((size_t)(t - 1) * B_SZ + b0) * H_DIM;
            for (int i = tid; i < 2048; i += 256)
                ((float4*)h_sh)[i] = ((const float4*)hp)[i];
        }
        __syncthreads();

        // ---- partial GEMM: acc[r][g] over k in [ks*128, ks*128+128) ----
        float acc[4][4];
#pragma unroll
        for (int r = 0; r < 4; r++)
#pragma unroll
            for (int g = 0; g < 4; g++) acc[r][g] = 0.0f;

        const float* wp  = wt + (size_t)(ks * 128) * 64 + jl * 4;
        const float* hp0 = h_sh + (size_t)(bq * 4) * 512 + ks * 128;

        for (int k4 = 0; k4 < 128; k4 += 4) {
            float hv[4][4];
            *(float4*)hv[0] = *(const float4*)(hp0 + 0 * 512 + k4);
            *(float4*)hv[1] = *(const float4*)(hp0 + 1 * 512 + k4);
            *(float4*)hv[2] = *(const float4*)(hp0 + 2 * 512 + k4);
            *(float4*)hv[3] = *(const float4*)(hp0 + 3 * 512 + k4);
#pragma unroll
            for (int kk = 0; kk < 4; kk++) {
                float4 w = *(const float4*)(wp + (size_t)(k4 + kk) * 64);
#pragma unroll
                for (int r = 0; r < 4; r++) {
                    float hvv = hv[r][kk];
                    acc[r][0] = fmaf(hvv, w.x, acc[r][0]);
                    acc[r][1] = fmaf(hvv, w.y, acc[r][1]);
                    acc[r][2] = fmaf(hvv, w.z, acc[r][2]);
                    acc[r][3] = fmaf(hvv, w.w, acc[r][3]);
                }
            }
        }

        // ---- write partials: red[((b_l*16 + jl)*4 + g)*4 + ks] ----
#pragma unroll
        for (int r = 0; r < 4; r++) {
            int b_l = bq * 4 + r;
#pragma unroll
            for (int g = 0; g < 4; g++)
                red[((b_l * 16 + jl) * 4 + g) * 4 + ks] = acc[r][g];
        }
        __syncthreads();

        // ---- reduce + gates + state update (thread owns (fb, fj)) ----
        {
            const float* xprow = g_xp + ((size_t)t * B_SZ + b0 + fb) * G4;
            float z[4];
#pragma unroll
            for (int g = 0; g < 4; g++) {
                float4 p = *(const float4*)&red[((fb * 16 + fj) * 4 + g) * 4];
                z[g] = (p.x + p.y) + (p.z + p.w) + xprow[g * H_DIM + j0 + fj];
            }
            float gg = tanhf(z[0]);
            float ii = 1.0f / (1.0f + expf(-z[1]));
            float ff = 1.0f / (1.0f + expf(-z[2]));
            float oo = 1.0f / (1.0f + expf(-z[3]));
            c_reg = gg * ii + c_reg * ff;
            hs[((size_t)t * B_SZ + b0 + fb) * H_DIM + j0 + fj] = tanhf(c_reg) * oo;
        }

        // ---- grid barrier (all h[t] visible before anyone reads it at t+1) ----
        __syncthreads();
        if (tid == 0) {
            __threadfence();
            unsigned prev = atomicAdd(&g_arrive, 1u);
            if (prev == (unsigned)(NBLK - 1)) {
                *(volatile unsigned*)&g_arrive = 0u;
                __threadfence();
                atomicAdd(&g_epoch, 1u);
            } else {
                unsigned want = (unsigned)(t + 1);
                while ((unsigned)(*(volatile unsigned*)&g_epoch - epoch_base) < want)
                    __nanosleep(64);
            }
            __threadfence();
        }
        __syncthreads();
    }
}

// ---------------- launch ----------------
extern "C" void kernel_launch(void* const* d_in, const int* in_sizes, int n_in,
                              void* d_out, int out_size)
{
    const float* embeds = (const float*)d_in[0];
    const float* w_gx   = (const float*)d_in[1];
    const float* w_gh   = (const float*)d_in[2];
    const float* b_g    = (const float*)d_in[3];
    const float* w_ix   = (const float*)d_in[4];
    const float* w_ih   = (const float*)d_in[5];
    const float* b_i    = (const float*)d_in[6];
    const float* w_fx   = (const float*)d_in[7];
    const float* w_fh   = (const float*)d_in[8];
    const float* b_f    = (const float*)d_in[9];
    const float* w_ox   = (const float*)d_in[10];
    const float* w_oh   = (const float*)d_in[11];
    const float* b_o    = (const float*)d_in[12];
    float* hs = (float*)d_out;

    static int smem_set = 0;
    const int scan_smem = (512 * 64 + 16 * 512 + 4096) * (int)sizeof(float); // 180224
    if (!smem_set) {
        cudaFuncSetAttribute(lstm_scan, cudaFuncAttributeMaxDynamicSharedMemorySize,
                             scan_smem);
        smem_set = 1;
    }

    pack_kernel<<<(E_DIM * G4 + 255) / 256, 256>>>(
        w_gx, w_ix, w_fx, w_ox, w_gh, w_ih, w_fh, w_oh, b_g, b_i, b_f, b_o);

    dim3 ggrid(G4 / 128, (T_LEN * B_SZ) / 128);   // (16, 512)
    gemm_xproj<<<ggrid, 256>>>(embeds);

    lstm_scan<<<NBLK, 256, scan_smem>>>(hs);
}

// round 16
// speedup vs baseline: 1.0982x; 1.0982x over previous
#include <cuda_runtime.h>
#include <cuda_bf16.h>
#include <math.h>
#include <stdint.h>

// LSTM: T=1024, B=64, E=512, H=512, fp32.
//   1) pack_kernel  : Wh fp32 (gate-major cols) + bias + WxT bf16 hi/lo [2048][512].
//   2) split_embeds : embeds -> bf16 hi/lo [65536][512].
//   3) gemm_xproj_mma: x_proj = embeds @ Wx + bias via mma.sync bf16 split-GEMM
//      (D = Ahi*Bhi + Ahi*Blo + Alo*Bhi, fp32 accum). Baseline PTX only —
//      tcgen05 is rejected by this harness's compute_103 PTX target.
//   4) lstm_scan    : ONE persistent kernel, 128 co-resident blocks, grid barrier.

#define T_LEN 1024
#define B_SZ  64
#define E_DIM 512
#define H_DIM 512
#define G4    2048
#define NBLK  128
#define MROWS (T_LEN * B_SZ)   // 65536

// -------- device-global scratch --------
__device__ __align__(16) float g_xp[(size_t)MROWS * G4];            // 512 MB
__device__ __align__(16) float g_wh[H_DIM * G4];
__device__ __align__(16) float g_bias[G4];
__device__ __align__(16) __nv_bfloat16 g_a_hi[(size_t)MROWS * E_DIM];
__device__ __align__(16) __nv_bfloat16 g_a_lo[(size_t)MROWS * E_DIM];
__device__ __align__(16) __nv_bfloat16 g_bT_hi[G4 * E_DIM];   // WxT [n][k]
__device__ __align__(16) __nv_bfloat16 g_bT_lo[G4 * E_DIM];
__device__ unsigned g_arrive = 0;
__device__ unsigned g_epoch  = 0;

// ======================= helpers (baseline PTX only) =======================
__device__ __forceinline__ uint32_t smem_u32(const void* p) {
    uint32_t a;
    asm("{ .reg .u64 t; cvta.to.shared.u64 t, %1; cvt.u32.u64 %0, t; }" : "=r"(a) : "l"(p));
    return a;
}
__device__ __forceinline__ void cp_async16(uint32_t dst, const void* src) {
    asm volatile("cp.async.cg.shared.global [%0], [%1], 16;" :: "r"(dst), "l"(src));
}
__device__ __forceinline__ void cp_commit() {
    asm volatile("cp.async.commit_group;" ::: "memory");
}
__device__ __forceinline__ void cp_wait0() {
    asm volatile("cp.async.wait_group 0;" ::: "memory");
}
__device__ __forceinline__ void ldmx4(uint32_t* r, uint32_t addr) {
    asm volatile("ldmatrix.sync.aligned.m8n8.x4.shared.b16 {%0,%1,%2,%3}, [%4];"
                 : "=r"(r[0]), "=r"(r[1]), "=r"(r[2]), "=r"(r[3]) : "r"(addr));
}
__device__ __forceinline__ void mma_bf16(float* c, const uint32_t* a, uint32_t b0, uint32_t b1) {
    asm volatile("mma.sync.aligned.m16n8k16.row.col.f32.bf16.bf16.f32 "
                 "{%0,%1,%2,%3}, {%4,%5,%6,%7}, {%8,%9}, {%0,%1,%2,%3};"
                 : "+f"(c[0]), "+f"(c[1]), "+f"(c[2]), "+f"(c[3])
                 : "r"(a[0]), "r"(a[1]), "r"(a[2]), "r"(a[3]), "r"(b0), "r"(b1));
}

// ======================= pack =======================
__global__ void pack_kernel(const float* __restrict__ wgx, const float* __restrict__ wix,
                            const float* __restrict__ wfx, const float* __restrict__ wox,
                            const float* __restrict__ wgh, const float* __restrict__ wih,
                            const float* __restrict__ wfh, const float* __restrict__ woh,
                            const float* __restrict__ bg,  const float* __restrict__ bi,
                            const float* __restrict__ bf,  const float* __restrict__ bo)
{
    int idx = blockIdx.x * blockDim.x + threadIdx.x;
    const int total = E_DIM * G4;
    if (idx < total) {
        int k = idx >> 11;
        int c = idx & 2047;
        int g = c >> 9;
        int j = c & 511;
        const float* sx = (g == 0) ? wgx : (g == 1) ? wix : (g == 2) ? wfx : wox;
        const float* sh = (g == 0) ? wgh : (g == 1) ? wih : (g == 2) ? wfh : woh;
        float vx = sx[k * H_DIM + j];
        __nv_bfloat16 hi = __float2bfloat16_rn(vx);
        __nv_bfloat16 lo = __float2bfloat16_rn(vx - __bfloat162float(hi));
        g_bT_hi[(size_t)c * E_DIM + k] = hi;
        g_bT_lo[(size_t)c * E_DIM + k] = lo;
        g_wh[idx] = sh[k * H_DIM + j];
    }
    if (idx < G4) {
        int g = idx >> 9, j = idx & 511;
        const float* sb = (g == 0) ? bg : (g == 1) ? bi : (g == 2) ? bf : bo;
        g_bias[idx] = sb[j];
    }
}

// ======================= split embeds =======================
__global__ void split_embeds(const float* __restrict__ A)
{
    size_t i = ((size_t)blockIdx.x * blockDim.x + threadIdx.x) * 4;
    if (i >= (size_t)MROWS * E_DIM) return;
    float4 v = *(const float4*)(A + i);
    __nv_bfloat162 h0, h1, l0, l1;
    float f;
    h0.x = __float2bfloat16_rn(v.x); f = v.x - __bfloat162float(h0.x); l0.x = __float2bfloat16_rn(f);
    h0.y = __float2bfloat16_rn(v.y); f = v.y - __bfloat162float(h0.y); l0.y = __float2bfloat16_rn(f);
    h1.x = __float2bfloat16_rn(v.z); f = v.z - __bfloat162float(h1.x); l1.x = __float2bfloat16_rn(f);
    h1.y = __float2bfloat16_rn(v.w); f = v.w - __bfloat162float(h1.y); l1.y = __float2bfloat16_rn(f);
    *(__nv_bfloat162*)(g_a_hi + i)     = h0;
    *(__nv_bfloat162*)(g_a_hi + i + 2) = h1;
    *(__nv_bfloat162*)(g_a_lo + i)     = l0;
    *(__nv_bfloat162*)(g_a_lo + i + 2) = l1;
}

// ======================= mma.sync split-GEMM =======================
// C[65536,2048] = A[65536,512] @ WxT^T + bias.  Block tile 128x128, BK=32 chunks,
// 8 warps (2x4), warp tile 64x32.  smem tile rows padded to 80B (40 halfwords):
// per buffer: Ahi|Alo|Bhi|Blo @ 128*80B = 10240B each -> 40960B; x2 buffers = 81920B.
#define TP  10240                  // bytes per tile (128 rows * 80)
#define BUFB 40960                 // bytes per buffer

__device__ __forceinline__ void issue_chunk(uint32_t sbuf, int m0, int n0, int c, int tid)
{
    const __nv_bfloat16* srcs[4] = { g_a_hi, g_a_lo, g_bT_hi, g_bT_lo };
    const int row0[4] = { m0, m0, n0, n0 };
#pragma unroll
    for (int i = 0; i < 8; i++) {
        int id   = tid + i * 256;
        int tile = id >> 9;               // 0..3
        int r    = (id >> 2) & 127;       // 0..127
        int seg  = id & 3;                // 0..3 (16B segments of 64B row)
        const __nv_bfloat16* src = srcs[tile] + (size_t)(row0[tile] + r) * E_DIM + c * 32 + seg * 8;
        cp_async16(sbuf + tile * TP + r * 80 + seg * 16, src);
    }
}

__global__ void __launch_bounds__(256, 1) gemm_xproj_mma()
{
    extern __shared__ __align__(16) char sm[];
    const uint32_t sbase = smem_u32(sm);

    const int tid  = threadIdx.x;
    const int wid  = tid >> 5;
    const int lane = tid & 31;
    const int wm = (wid >> 2) * 64;       // warp m offset 0/64
    const int wn = (wid & 3) * 32;        // warp n offset 0/32/64/96
    const int n0 = blockIdx.x * 128;
    const int m0 = blockIdx.y * 128;

    float acc[4][4][4];
#pragma unroll
    for (int mi = 0; mi < 4; mi++)
#pragma unroll
        for (int ni = 0; ni < 4; ni++)
#pragma unroll
            for (int q = 0; q < 4; q++) acc[mi][ni][q] = 0.0f;

    // per-lane ldmatrix address offsets (within a tile)
    const int lrow = lane & 15;
    const int lcol16 = (lane >> 4) * 16;  // byte offset of k-half

    issue_chunk(sbase, m0, n0, 0, tid);
    cp_commit();

#pragma unroll 1
    for (int c = 0; c < 16; c++) {
        cp_wait0();
        __syncthreads();                  // chunk c ready; prior mma reads done
        const uint32_t sbuf = sbase + (c & 1) * BUFB;
        if (c < 15) {
            issue_chunk(sbase + ((c + 1) & 1) * BUFB, m0, n0, c + 1, tid);
            cp_commit();
        }

#pragma unroll
        for (int kk = 0; kk < 2; kk++) {
            const uint32_t kb = kk * 32 + lcol16;   // byte offset in row for this k16
            uint32_t ah[4][4], al[4][4], bh[2][4], bl[2][4];
#pragma unroll
            for (int mi = 0; mi < 4; mi++) {
                uint32_t ra = (wm + mi * 16 + lrow) * 80 + kb;
                ldmx4(ah[mi], sbuf + 0 * TP + ra);
                ldmx4(al[mi], sbuf + 1 * TP + ra);
            }
#pragma unroll
            for (int pi = 0; pi < 2; pi++) {
                uint32_t rb = (wn + pi * 16 + lrow) * 80 + kb;
                ldmx4(bh[pi], sbuf + 2 * TP + rb);
                ldmx4(bl[pi], sbuf + 3 * TP + rb);
            }
#pragma unroll
            for (int mi = 0; mi < 4; mi++)
#pragma unroll
                for (int ni = 0; ni < 4; ni++) {
                    const int pi = ni >> 1, wq = ni & 1;
                    mma_bf16(acc[mi][ni], ah[mi], bh[pi][wq], bh[pi][wq + 2]);
                    mma_bf16(acc[mi][ni], ah[mi], bl[pi][wq], bl[pi][wq + 2]);
                    mma_bf16(acc[mi][ni], al[mi], bh[pi][wq], bh[pi][wq + 2]);
                }
        }
        __syncthreads();                  // done reading sbuf before c+2 overwrites it
    }

    // epilogue: c-frag (row = lane/4 [+8], col = (lane%4)*2) + bias -> g_xp
    const int crow = lane >> 2;
    const int ccol = (lane & 3) * 2;
#pragma unroll
    for (int mi = 0; mi < 4; mi++) {
#pragma unroll
        for (int ni = 0; ni < 4; ni++) {
            int m = m0 + wm + mi * 16 + crow;
            int n = n0 + wn + ni * 8 + ccol;
            float b0 = g_bias[n], b1 = g_bias[n + 1];
            float2 v0 = make_float2(acc[mi][ni][0] + b0, acc[mi][ni][1] + b1);
            float2 v1 = make_float2(acc[mi][ni][2] + b0, acc[mi][ni][3] + b1);
            *(float2*)(g_xp + (size_t)m * G4 + n)       = v0;
            *(float2*)(g_xp + (size_t)(m + 8) * G4 + n) = v1;
        }
    }
}

// ======================= persistent LSTM scan (unchanged) =======================
__global__ void __launch_bounds__(256, 1) lstm_scan(float* __restrict__ hs)
{
    extern __shared__ __align__(16) float smem[];
    float* wt   = smem;
    float* h_sh = wt + 512 * 64;
    float* red  = h_sh + 16 * 512;

    const int tid = threadIdx.x;
    const int bt  = blockIdx.x >> 5;
    const int jt  = blockIdx.x & 31;
    const int b0  = bt * 16;
    const int j0  = jt * 16;

    const int ks = tid >> 6;
    const int bq = (tid >> 4) & 3;
    const int jl = tid & 15;
    const int fb = tid >> 4;
    const int fj = tid & 15;

    for (int i = tid; i < 512 * 16; i += 256) {
        int k = i >> 4;
        int s = i & 15;
        int g = s >> 2;
        int q = s & 3;
        float4 v = *(const float4*)(g_wh + (size_t)k * G4 + g * H_DIM + j0 + q * 4);
        float* d = wt + k * 64 + q * 16 + g;
        d[0]  = v.x;
        d[4]  = v.y;
        d[8]  = v.z;
        d[12] = v.w;
    }

    unsigned epoch_base = 0;
    if (tid == 0) epoch_base = *(volatile unsigned*)&g_epoch;

    float c_reg = 0.0f;

    for (int t = 0; t < T_LEN; t++) {
        if (t == 0) {
            float4 z4 = make_float4(0.f, 0.f, 0.f, 0.f);
            for (int i = tid; i < 2048; i += 256)
                ((float4*)h_sh)[i] = z4;
        } else {
            const float* hp = hs + ((size_t)(t - 1) * B_SZ + b0) * H_DIM;
            for (int i = tid; i < 2048; i += 256)
                ((float4*)h_sh)[i] = ((const float4*)hp)[i];
        }
        __syncthreads();

        float acc[4][4];
#pragma unroll
        for (int r = 0; r < 4; r++)
#pragma unroll
            for (int g = 0; g < 4; g++) acc[r][g] = 0.0f;

        const float* wp  = wt + (size_t)(ks * 128) * 64 + jl * 4;
        const float* hp0 = h_sh + (size_t)(bq * 4) * 512 + ks * 128;

        for (int k4 = 0; k4 < 128; k4 += 4) {
            float hv[4][4];
            *(float4*)hv[0] = *(const float4*)(hp0 + 0 * 512 + k4);
            *(float4*)hv[1] = *(const float4*)(hp0 + 1 * 512 + k4);
            *(float4*)hv[2] = *(const float4*)(hp0 + 2 * 512 + k4);
            *(float4*)hv[3] = *(const float4*)(hp0 + 3 * 512 + k4);
#pragma unroll
            for (int kk = 0; kk < 4; kk++) {
                float4 w = *(const float4*)(wp + (size_t)(k4 + kk) * 64);
#pragma unroll
                for (int r = 0; r < 4; r++) {
                    float hvv = hv[r][kk];
                    acc[r][0] = fmaf(hvv, w.x, acc[r][0]);
                    acc[r][1] = fmaf(hvv, w.y, acc[r][1]);
                    acc[r][2] = fmaf(hvv, w.z, acc[r][2]);
                    acc[r][3] = fmaf(hvv, w.w, acc[r][3]);
                }
            }
        }

#pragma unroll
        for (int r = 0; r < 4; r++) {
            int b_l = bq * 4 + r;
#pragma unroll
            for (int g = 0; g < 4; g++)
                red[((b_l * 16 + jl) * 4 + g) * 4 + ks] = acc[r][g];
        }
        __syncthreads();

        {
            const float* xprow = g_xp + ((size_t)t * B_SZ + b0 + fb) * G4;
            float z[4];
#pragma unroll
            for (int g = 0; g < 4; g++) {
                float4 p = *(const float4*)&red[((fb * 16 + fj) * 4 + g) * 4];
                z[g] = (p.x + p.y) + (p.z + p.w) + xprow[g * H_DIM + j0 + fj];
            }
            float gg = tanhf(z[0]);
            float ii = 1.0f / (1.0f + expf(-z[1]));
            float ff = 1.0f / (1.0f + expf(-z[2]));
            float oo = 1.0f / (1.0f + expf(-z[3]));
            c_reg = gg * ii + c_reg * ff;
            hs[((size_t)t * B_SZ + b0 + fb) * H_DIM + j0 + fj] = tanhf(c_reg) * oo;
        }

        __syncthreads();
        if (tid == 0) {
            __threadfence();
            unsigned prev = atomicAdd(&g_arrive, 1u);
            if (prev == (unsigned)(NBLK - 1)) {
                *(volatile unsigned*)&g_arrive = 0u;
                __threadfence();
                atomicAdd(&g_epoch, 1u);
            } else {
                unsigned want = (unsigned)(t + 1);
                while ((unsigned)(*(volatile unsigned*)&g_epoch - epoch_base) < want)
                    __nanosleep(64);
            }
            __threadfence();
        }
        __syncthreads();
    }
}

// ======================= launch =======================
extern "C" void kernel_launch(void* const* d_in, const int* in_sizes, int n_in,
                              void* d_out, int out_size)
{
    const float* embeds = (const float*)d_in[0];
    const float* w_gx   = (const float*)d_in[1];
    const float* w_gh   = (const float*)d_in[2];
    const float* b_g    = (const float*)d_in[3];
    const float* w_ix   = (const float*)d_in[4];
    const float* w_ih   = (const float*)d_in[5];
    const float* b_i    = (const float*)d_in[6];
    const float* w_fx   = (const float*)d_in[7];
    const float* w_fh   = (const float*)d_in[8];
    const float* b_f    = (const float*)d_in[9];
    const float* w_ox   = (const float*)d_in[10];
    const float* w_oh   = (const float*)d_in[11];
    const float* b_o    = (const float*)d_in[12];
    float* hs = (float*)d_out;

    static int attr_set = 0;
    const int scan_smem = (512 * 64 + 16 * 512 + 4096) * (int)sizeof(float); // 180224
    const int gemm_smem = 2 * BUFB;                                          // 81920
    if (!attr_set) {
        cudaFuncSetAttribute(lstm_scan, cudaFuncAttributeMaxDynamicSharedMemorySize, scan_smem);
        cudaFuncSetAttribute(gemm_xproj_mma, cudaFuncAttributeMaxDynamicSharedMemorySize, gemm_smem);
        attr_set = 1;
    }

    pack_kernel<<<(E_DIM * G4 + 255) / 256, 256>>>(
        w_gx, w_ix, w_fx, w_ox, w_gh, w_ih, w_fh, w_oh, b_g, b_i, b_f, b_o);

    split_embeds<<<((size_t)MROWS * E_DIM / 4 + 255) / 256, 256>>>(embeds);

    dim3 ggrid(G4 / 128, MROWS / 128);   // (16, 512)
    gemm_xproj_mma<<<ggrid, 256, gemm_smem>>>();

    lstm_scan<<<NBLK, 256, scan_smem>>>(hs);
}

// round 17
// speedup vs baseline: 1.6552x; 1.5072x over previous
#include <cuda_runtime.h>
#include <cuda_bf16.h>
#include <math.h>
#include <stdint.h>

// LSTM: T=1024, B=64, E=512, H=512, fp32.
//   1) pack_kernel   : bias + WxT bf16 hi/lo [2048][512] + WhT bf16 hi/lo [2048][512].
//   2) split_embeds  : embeds -> bf16 hi/lo [65536][512].
//   3) gemm_xproj_mma: x_proj = embeds @ Wx + bias via mma.sync bf16 split-GEMM.
//   4) lstm_scan_tc  : persistent kernel, 128 blocks = 2 batch-tiles x 64 j-slices.
//      h @ Wh on tensor cores (bf16 hi/lo split, fp32 accum); Wh slice resident in
//      smem; h carried as bf16 hi/lo in double-buffered globals; grid barrier/step.

#define T_LEN 1024
#define B_SZ  64
#define E_DIM 512
#define H_DIM 512
#define G4    2048
#define MROWS (T_LEN * B_SZ)   // 65536
#define NBLK2 128              // scan blocks (must be <= 148, co-resident)

// -------- device-global scratch --------
__device__ __align__(16) float g_xp[(size_t)MROWS * G4];            // 512 MB
__device__ __align__(16) float g_bias[G4];
__device__ __align__(16) __nv_bfloat16 g_a_hi[(size_t)MROWS * E_DIM];
__device__ __align__(16) __nv_bfloat16 g_a_lo[(size_t)MROWS * E_DIM];
__device__ __align__(16) __nv_bfloat16 g_bT_hi[G4 * E_DIM];   // WxT [n][k]
__device__ __align__(16) __nv_bfloat16 g_bT_lo[G4 * E_DIM];
__device__ __align__(16) __nv_bfloat16 g_wT_hi[G4 * H_DIM];   // WhT [n][k]
__device__ __align__(16) __nv_bfloat16 g_wT_lo[G4 * H_DIM];
__device__ __align__(16) __nv_bfloat16 g_hh[2][B_SZ * H_DIM]; // h history hi (dbl buf)
__device__ __align__(16) __nv_bfloat16 g_hl[2][B_SZ * H_DIM]; // h history lo
__device__ unsigned g_arrive = 0;
__device__ unsigned g_epoch  = 0;

// ======================= helpers (baseline PTX only) =======================
__device__ __forceinline__ uint32_t smem_u32(const void* p) {
    uint32_t a;
    asm("{ .reg .u64 t; cvta.to.shared.u64 t, %1; cvt.u32.u64 %0, t; }" : "=r"(a) : "l"(p));
    return a;
}
__device__ __forceinline__ void cp_async16(uint32_t dst, const void* src) {
    asm volatile("cp.async.cg.shared.global [%0], [%1], 16;" :: "r"(dst), "l"(src));
}
__device__ __forceinline__ void cp_commit() {
    asm volatile("cp.async.commit_group;" ::: "memory");
}
__device__ __forceinline__ void cp_wait0() {
    asm volatile("cp.async.wait_group 0;" ::: "memory");
}
__device__ __forceinline__ void ldmx4(uint32_t* r, uint32_t addr) {
    asm volatile("ldmatrix.sync.aligned.m8n8.x4.shared.b16 {%0,%1,%2,%3}, [%4];"
                 : "=r"(r[0]), "=r"(r[1]), "=r"(r[2]), "=r"(r[3]) : "r"(addr));
}
__device__ __forceinline__ void mma_bf16(float* c, const uint32_t* a, uint32_t b0, uint32_t b1) {
    asm volatile("mma.sync.aligned.m16n8k16.row.col.f32.bf16.bf16.f32 "
                 "{%0,%1,%2,%3}, {%4,%5,%6,%7}, {%8,%9}, {%0,%1,%2,%3};"
                 : "+f"(c[0]), "+f"(c[1]), "+f"(c[2]), "+f"(c[3])
                 : "r"(a[0]), "r"(a[1]), "r"(a[2]), "r"(a[3]), "r"(b0), "r"(b1));
}

// ======================= pack =======================
__global__ void pack_kernel(const float* __restrict__ wgx, const float* __restrict__ wix,
                            const float* __restrict__ wfx, const float* __restrict__ wox,
                            const float* __restrict__ wgh, const float* __restrict__ wih,
                            const float* __restrict__ wfh, const float* __restrict__ woh,
                            const float* __restrict__ bg,  const float* __restrict__ bi,
                            const float* __restrict__ bf,  const float* __restrict__ bo)
{
    int idx = blockIdx.x * blockDim.x + threadIdx.x;
    const int total = E_DIM * G4;
    if (idx < total) {
        int k = idx >> 11;
        int c = idx & 2047;
        int g = c >> 9;
        int j = c & 511;
        const float* sx = (g == 0) ? wgx : (g == 1) ? wix : (g == 2) ? wfx : wox;
        const float* sh = (g == 0) ? wgh : (g == 1) ? wih : (g == 2) ? wfh : woh;
        float vx = sx[k * H_DIM + j];
        __nv_bfloat16 xhi = __float2bfloat16_rn(vx);
        g_bT_hi[(size_t)c * E_DIM + k] = xhi;
        g_bT_lo[(size_t)c * E_DIM + k] = __float2bfloat16_rn(vx - __bfloat162float(xhi));
        float vh = sh[k * H_DIM + j];
        __nv_bfloat16 whi = __float2bfloat16_rn(vh);
        g_wT_hi[(size_t)c * H_DIM + k] = whi;
        g_wT_lo[(size_t)c * H_DIM + k] = __float2bfloat16_rn(vh - __bfloat162float(whi));
    }
    if (idx < G4) {
        int g = idx >> 9, j = idx & 511;
        const float* sb = (g == 0) ? bg : (g == 1) ? bi : (g == 2) ? bf : bo;
        g_bias[idx] = sb[j];
    }
}

// ======================= split embeds =======================
__global__ void split_embeds(const float* __restrict__ A)
{
    size_t i = ((size_t)blockIdx.x * blockDim.x + threadIdx.x) * 4;
    if (i >= (size_t)MROWS * E_DIM) return;
    float4 v = *(const float4*)(A + i);
    __nv_bfloat162 h0, h1, l0, l1;
    float f;
    h0.x = __float2bfloat16_rn(v.x); f = v.x - __bfloat162float(h0.x); l0.x = __float2bfloat16_rn(f);
    h0.y = __float2bfloat16_rn(v.y); f = v.y - __bfloat162float(h0.y); l0.y = __float2bfloat16_rn(f);
    h1.x = __float2bfloat16_rn(v.z); f = v.z - __bfloat162float(h1.x); l1.x = __float2bfloat16_rn(f);
    h1.y = __float2bfloat16_rn(v.w); f = v.w - __bfloat162float(h1.y); l1.y = __float2bfloat16_rn(f);
    *(__nv_bfloat162*)(g_a_hi + i)     = h0;
    *(__nv_bfloat162*)(g_a_hi + i + 2) = h1;
    *(__nv_bfloat162*)(g_a_lo + i)     = l0;
    *(__nv_bfloat162*)(g_a_lo + i + 2) = l1;
}

// ======================= mma.sync split-GEMM (x_proj) =======================
#define TP  10240
#define BUFB 40960

__device__ __forceinline__ void issue_chunk(uint32_t sbuf, int m0, int n0, int c, int tid)
{
    const __nv_bfloat16* srcs[4] = { g_a_hi, g_a_lo, g_bT_hi, g_bT_lo };
    const int row0[4] = { m0, m0, n0, n0 };
#pragma unroll
    for (int i = 0; i < 8; i++) {
        int id   = tid + i * 256;
        int tile = id >> 9;
        int r    = (id >> 2) & 127;
        int seg  = id & 3;
        const __nv_bfloat16* src = srcs[tile] + (size_t)(row0[tile] + r) * E_DIM + c * 32 + seg * 8;
        cp_async16(sbuf + tile * TP + r * 80 + seg * 16, src);
    }
}

__global__ void __launch_bounds__(256, 1) gemm_xproj_mma()
{
    extern __shared__ __align__(16) char sm[];
    const uint32_t sbase = smem_u32(sm);

    const int tid  = threadIdx.x;
    const int wid  = tid >> 5;
    const int lane = tid & 31;
    const int wm = (wid >> 2) * 64;
    const int wn = (wid & 3) * 32;
    const int n0 = blockIdx.x * 128;
    const int m0 = blockIdx.y * 128;

    float acc[4][4][4];
#pragma unroll
    for (int mi = 0; mi < 4; mi++)
#pragma unroll
        for (int ni = 0; ni < 4; ni++)
#pragma unroll
            for (int q = 0; q < 4; q++) acc[mi][ni][q] = 0.0f;

    const int lrow = lane & 15;
    const int lcol16 = (lane >> 4) * 16;

    issue_chunk(sbase, m0, n0, 0, tid);
    cp_commit();

#pragma unroll 1
    for (int c = 0; c < 16; c++) {
        cp_wait0();
        __syncthreads();
        const uint32_t sbuf = sbase + (c & 1) * BUFB;
        if (c < 15) {
            issue_chunk(sbase + ((c + 1) & 1) * BUFB, m0, n0, c + 1, tid);
            cp_commit();
        }

#pragma unroll
        for (int kk = 0; kk < 2; kk++) {
            const uint32_t kb = kk * 32 + lcol16;
            uint32_t ah[4][4], al[4][4], bh[2][4], bl[2][4];
#pragma unroll
            for (int mi = 0; mi < 4; mi++) {
                uint32_t ra = (wm + mi * 16 + lrow) * 80 + kb;
                ldmx4(ah[mi], sbuf + 0 * TP + ra);
                ldmx4(al[mi], sbuf + 1 * TP + ra);
            }
#pragma unroll
            for (int pi = 0; pi < 2; pi++) {
                uint32_t rb = (wn + pi * 16 + lrow) * 80 + kb;
                ldmx4(bh[pi], sbuf + 2 * TP + rb);
                ldmx4(bl[pi], sbuf + 3 * TP + rb);
            }
#pragma unroll
            for (int mi = 0; mi < 4; mi++)
#pragma unroll
                for (int ni = 0; ni < 4; ni++) {
                    const int pi = ni >> 1, wq = ni & 1;
                    mma_bf16(acc[mi][ni], ah[mi], bh[pi][wq], bh[pi][wq + 2]);
                    mma_bf16(acc[mi][ni], ah[mi], bl[pi][wq], bl[pi][wq + 2]);
                    mma_bf16(acc[mi][ni], al[mi], bh[pi][wq], bh[pi][wq + 2]);
                }
        }
        __syncthreads();
    }

    const int crow = lane >> 2;
    const int ccol = (lane & 3) * 2;
#pragma unroll
    for (int mi = 0; mi < 4; mi++) {
#pragma unroll
        for (int ni = 0; ni < 4; ni++) {
            int m = m0 + wm + mi * 16 + crow;
            int n = n0 + wn + ni * 8 + ccol;
            float b0 = g_bias[n], b1 = g_bias[n + 1];
            float2 v0 = make_float2(acc[mi][ni][0] + b0, acc[mi][ni][1] + b1);
            float2 v1 = make_float2(acc[mi][ni][2] + b0, acc[mi][ni][3] + b1);
            *(float2*)(g_xp + (size_t)m * G4 + n)       = v0;
            *(float2*)(g_xp + (size_t)(m + 8) * G4 + n) = v1;
        }
    }
}

// ======================= tensor-core persistent LSTM scan =======================
// 128 blocks: bm = blk>>6 (batch tile of 32), nb = blk&63 -> j0 = nb*8 (8 j x 4 gates
// = 32 packed cols, packed col c = jl*4+g  <->  global gate col g*512 + j0 + jl).
// smem: A(h) hi/lo 2x32KB | B(Wh) hi/lo 2x32KB | red 16KB = 147456 B.
// Swizzle: 16B chunk c in a 1024B row r stored at ((c ^ (r&7)) << 4).
#define SA_HI 0
#define SA_LO 32768
#define SB_HI 65536
#define SB_LO 98304
#define SRED  131072
#define SCAN_SMEM 147456

__global__ void __launch_bounds__(256, 1) lstm_scan_tc(float* __restrict__ hs)
{
    extern __shared__ __align__(16) char sm[];
    const uint32_t sbase = smem_u32(sm);
    float* red = (float*)(sm + SRED);

    const int tid  = threadIdx.x;
    const int wid  = tid >> 5;
    const int lane = tid & 31;
    const int bm = blockIdx.x >> 6;        // 0..1
    const int nb = blockIdx.x & 63;        // 0..63
    const int j0 = nb * 8;

    const int mi = wid & 1;                // m-tile (16 rows)
    const int kg = wid >> 1;               // k-group (128 wide)
    const int mbase = mi * 16;
    const int lrow = lane & 15;
    const int lhalf16 = (lane >> 4) * 16;  // byte offset of k-half for ldmatrix

    // ---- stage Wh slice once (32 packed cols x 512 k, hi/lo) ----
    for (int i = tid; i < 4096; i += 256) {
        int v   = i >> 11;                 // 0 hi, 1 lo
        int id  = i & 2047;
        int row = id >> 6;                 // packed col 0..31
        int c   = id & 63;                 // 16B chunk
        int gr  = (row & 3) * H_DIM + j0 + (row >> 2);   // global gate col
        const __nv_bfloat16* src = (v ? g_wT_lo : g_wT_hi) + (size_t)gr * H_DIM + c * 8;
        cp_async16(sbase + (v ? SB_LO : SB_HI) + row * 1024 + ((c ^ (row & 7)) << 4), src);
    }
    cp_commit();
    cp_wait0();
    __syncthreads();

    unsigned epoch_base = 0;
    if (tid == 0) epoch_base = *(volatile unsigned*)&g_epoch;

    // this thread's output element
    const int ob = tid >> 3;               // local batch row 0..31
    const int oj = tid & 7;                // local j 0..7
    const int bglob = bm * 32 + ob;
    const int jglob = j0 + oj;
    float c_reg = 0.0f;

    for (int t = 0; t < T_LEN; t++) {
        const int rd = (t & 1) ^ 1;        // h[t-1] buffer
        const int wr = t & 1;              // h[t] buffer

        if (t > 0) {
            // ---- stage h tile: 32 rows x 512 bf16, hi/lo ----
            for (int i = tid; i < 4096; i += 256) {
                int v   = i >> 11;
                int id  = i & 2047;
                int row = id >> 6;
                int c   = id & 63;
                const __nv_bfloat16* src =
                    (v ? g_hl[rd] : g_hh[rd]) + (size_t)(bm * 32 + row) * H_DIM + c * 8;
                cp_async16(sbase + (v ? SA_LO : SA_HI) + row * 1024 + ((c ^ (row & 7)) << 4), src);
            }
            cp_commit();
            cp_wait0();
            __syncthreads();

            // ---- warp (mi, kg): m16 x n32 over K128 ----
            float acc[4][4];
#pragma unroll
            for (int ni = 0; ni < 4; ni++)
#pragma unroll
                for (int q = 0; q < 4; q++) acc[ni][q] = 0.0f;

#pragma unroll
            for (int kk = 0; kk < 8; kk++) {
                const int kbyte = kg * 256 + kk * 32 + lhalf16;
                const int c16 = kbyte >> 4;
                uint32_t ah[4], al[4], bh[2][4], bl[2][4];
                {
                    int r = mbase + lrow;
                    uint32_t off = r * 1024 + (((c16) ^ (r & 7)) << 4);
                    ldmx4(ah, sbase + SA_HI + off);
                    ldmx4(al, sbase + SA_LO + off);
                }
#pragma unroll
                for (int pi = 0; pi < 2; pi++) {
                    int r = pi * 16 + lrow;
                    uint32_t off = r * 1024 + (((c16) ^ (r & 7)) << 4);
                    ldmx4(bh[pi], sbase + SB_HI + off);
                    ldmx4(bl[pi], sbase + SB_LO + off);
                }
#pragma unroll
                for (int ni = 0; ni < 4; ni++) {
                    const int pi = ni >> 1, wq = ni & 1;
                    mma_bf16(acc[ni], ah, bh[pi][wq], bh[pi][wq + 2]);
                    mma_bf16(acc[ni], ah, bl[pi][wq], bl[pi][wq + 2]);
                    mma_bf16(acc[ni], al, bh[pi][wq], bh[pi][wq + 2]);
                }
            }

            // ---- dump partials: red[(b_local*32 + n)*4 + kg] ----
            const int r0 = lane >> 2;
            const int cc = (lane & 3) * 2;
#pragma unroll
            for (int ni = 0; ni < 4; ni++) {
                int n = ni * 8 + cc;
                red[((mbase + r0) * 32 + n) * 4 + kg]           = acc[ni][0];
                red[((mbase + r0) * 32 + n + 1) * 4 + kg]       = acc[ni][1];
                red[((mbase + r0 + 8) * 32 + n) * 4 + kg]       = acc[ni][2];
                red[((mbase + r0 + 8) * 32 + n + 1) * 4 + kg]   = acc[ni][3];
            }
            __syncthreads();
        }

        // ---- reduce + gates + state update ----
        {
            const float* xprow = g_xp + ((size_t)t * B_SZ + bglob) * G4;
            float z[4];
#pragma unroll
            for (int g = 0; g < 4; g++) {
                float s = xprow[g * H_DIM + jglob];
                if (t > 0) {
                    float4 p = *(const float4*)&red[(ob * 32 + (oj * 4 + g)) * 4];
                    s += (p.x + p.y) + (p.z + p.w);
                }
                z[g] = s;
            }
            float gg = tanhf(z[0]);
            float ii = 1.0f / (1.0f + expf(-z[1]));
            float ff = 1.0f / (1.0f + expf(-z[2]));
            float oo = 1.0f / (1.0f + expf(-z[3]));
            c_reg = gg * ii + c_reg * ff;
            float hn = tanhf(c_reg) * oo;

            hs[((size_t)t * B_SZ + bglob) * H_DIM + jglob] = hn;
            __nv_bfloat16 hhi = __float2bfloat16_rn(hn);
            g_hh[wr][(size_t)bglob * H_DIM + jglob] = hhi;
            g_hl[wr][(size_t)bglob * H_DIM + jglob] =
                __float2bfloat16_rn(hn - __bfloat162float(hhi));
        }

        // ---- grid barrier ----
        __syncthreads();
        if (tid == 0) {
            __threadfence();
            unsigned prev = atomicAdd(&g_arrive, 1u);
            if (prev == (unsigned)(NBLK2 - 1)) {
                *(volatile unsigned*)&g_arrive = 0u;
                __threadfence();
                atomicAdd(&g_epoch, 1u);
            } else {
                unsigned want = (unsigned)(t + 1);
                while ((unsigned)(*(volatile unsigned*)&g_epoch - epoch_base) < want)
                    __nanosleep(32);
            }
            __threadfence();
        }
        __syncthreads();
    }
}

// ======================= launch =======================
extern "C" void kernel_launch(void* const* d_in, const int* in_sizes, int n_in,
                              void* d_out, int out_size)
{
    const float* embeds = (const float*)d_in[0];
    const float* w_gx   = (const float*)d_in[1];
    const float* w_gh   = (const float*)d_in[2];
    const float* b_g    = (const float*)d_in[3];
    const float* w_ix   = (const float*)d_in[4];
    const float* w_ih   = (const float*)d_in[5];
    const float* b_i    = (const float*)d_in[6];
    const float* w_fx   = (const float*)d_in[7];
    const float* w_fh   = (const float*)d_in[8];
    const float* b_f    = (const float*)d_in[9];
    const float* w_ox   = (const float*)d_in[10];
    const float* w_oh   = (const float*)d_in[11];
    const float* b_o    = (const float*)d_in[12];
    float* hs = (float*)d_out;

    static int attr_set = 0;
    const int gemm_smem = 2 * BUFB;       // 81920
    if (!attr_set) {
        cudaFuncSetAttribute(gemm_xproj_mma, cudaFuncAttributeMaxDynamicSharedMemorySize, gemm_smem);
        cudaFuncSetAttribute(lstm_scan_tc, cudaFuncAttributeMaxDynamicSharedMemorySize, SCAN_SMEM);
        attr_set = 1;
    }

    pack_kernel<<<(E_DIM * G4 + 255) / 256, 256>>>(
        w_gx, w_ix, w_fx, w_ox, w_gh, w_ih, w_fh, w_oh, b_g, b_i, b_f, b_o);

    split_embeds<<<((size_t)MROWS * E_DIM / 4 + 255) / 256, 256>>>(embeds);

    dim3 ggrid(G4 / 128, MROWS / 128);
    gemm_xproj_mma<<<ggrid, 256, gemm_smem>>>();

    lstm_scan_tc<<<NBLK2, 256, SCAN_SMEM>>>(hs);
}